// round 2
// baseline (speedup 1.0000x reference)
#include <cuda_runtime.h>

#define NN 40000
#define NE 320000
#define NG 64
#define IND 128
#define H4 256
#define OUTD 128
#define CAT 512

// ---------------- scratch (device globals; no allocation allowed) ----------------
__device__ int   g_outcnt[NN];
__device__ int   g_incnt[NN];
__device__ int   g_cursor[NN];
__device__ int   g_rowptr[NN + 1];
__device__ float g_outinv[NN];
__device__ float g_ininv[NN];
__device__ int   g_es[NE];     // edge src, CSR-ordered by dst
__device__ float g_ec[NE];     // edge coef = max(w)*out_inv[src], CSR-ordered
__device__ float g_agg1[NN * IND];
__device__ float g_x1f1[NN * CAT];
__device__ float g_y2[NN * H4];
__device__ float g_x2[NN * H4];
__device__ float g_y3[NN * OUTD];
__device__ float g_readout[NG * OUTD];

// ---------------- small helpers ----------------
__device__ __forceinline__ unsigned long long packff(float lo, float hi) {
    return ((unsigned long long)__float_as_uint(hi) << 32) | (unsigned long long)__float_as_uint(lo);
}
__device__ __forceinline__ float lo32(unsigned long long u) { return __uint_as_float((unsigned)u); }
__device__ __forceinline__ float hi32(unsigned long long u) { return __uint_as_float((unsigned)(u >> 32)); }
__device__ __forceinline__ void ffma2(unsigned long long& d, unsigned long long a, unsigned long long b) {
    // Blackwell packed fp32x2 FMA (FFMA2) — 2x fp32 throughput
    asm volatile("fma.rn.f32x2 %0, %1, %2, %0;" : "+l"(d) : "l"(a), "l"(b));
}

// ---------------- setup kernels ----------------
__global__ void k_zero() {
    int i = blockIdx.x * blockDim.x + threadIdx.x;
    if (i < NN) { g_outcnt[i] = 0; g_incnt[i] = 0; g_cursor[i] = 0; }
    if (i < NG * OUTD) g_readout[i] = 0.f;
}

__global__ void k_deg(const int* __restrict__ src, const int* __restrict__ dst) {
    int e = blockIdx.x * blockDim.x + threadIdx.x;
    if (e < NE) {
        atomicAdd(&g_outcnt[src[e]], 1);
        atomicAdd(&g_incnt[dst[e]], 1);
    }
}

__global__ void k_inv() {
    int i = blockIdx.x * blockDim.x + threadIdx.x;
    if (i < NN) {
        g_outinv[i] = rsqrtf((float)max(g_outcnt[i], 1));
        g_ininv[i]  = rsqrtf((float)max(g_incnt[i], 1));
    }
}

// single-block exclusive scan of in-degree -> row_ptr (N+1 entries)
__global__ void k_scan() {
    __shared__ int sums[1024];
    const int CH = 40;  // 1024*40 = 40960 >= NN+1
    int t = threadIdx.x;
    int base = t * CH;
    int local[CH];
    int s = 0;
#pragma unroll
    for (int i = 0; i < CH; i++) {
        int idx = base + i;
        local[i] = s;
        int v = (idx < NN) ? g_incnt[idx] : 0;
        s += v;
    }
    sums[t] = s;
    __syncthreads();
    for (int off = 1; off < 1024; off <<= 1) {
        int v = (t >= off) ? sums[t - off] : 0;
        __syncthreads();
        sums[t] += v;
        __syncthreads();
    }
    int off0 = (t == 0) ? 0 : sums[t - 1];
#pragma unroll
    for (int i = 0; i < CH; i++) {
        int idx = base + i;
        if (idx <= NN) g_rowptr[idx] = off0 + local[i];
    }
}

__global__ void k_place(const int* __restrict__ src, const int* __restrict__ dst,
                        const float* __restrict__ w) {
    int e = blockIdx.x * blockDim.x + threadIdx.x;
    if (e >= NE) return;
    float4 ww = *(const float4*)(w + 4 * e);
    float m = fmaxf(fmaxf(ww.x, ww.y), fmaxf(ww.z, ww.w));
    int d = dst[e];
    int s = src[e];
    int pos = g_rowptr[d] + atomicAdd(&g_cursor[d], 1);
    g_es[pos] = s;
    g_ec[pos] = m * g_outinv[s];
}

// ---------------- aggregation: one warp per dst node (gather form, no f32 atomics) ----------------
// MODE 0: out = in_inv * sum            (pre-GEMM agg, layer 1)
// MODE 1: out = relu(in_inv * sum)      (layers 2)
// MODE 2: relu(in_inv*sum) -> atomicAdd into per-graph readout (layer 3, x3 never stored)
template <int D, int MODE>
__global__ void k_agg(const float* __restrict__ in, float* __restrict__ out,
                      const int* __restrict__ gid) {
    int warp = (blockIdx.x * blockDim.x + threadIdx.x) >> 5;
    int lane = threadIdx.x & 31;
    if (warp >= NN) return;
    int beg = g_rowptr[warp];
    int end = g_rowptr[warp + 1];
    constexpr int V = D / 128;
    float4 acc[V];
#pragma unroll
    for (int v = 0; v < V; v++) acc[v] = make_float4(0.f, 0.f, 0.f, 0.f);
    for (int e = beg; e < end; e++) {
        int s = g_es[e];
        float c = g_ec[e];
        const float4* p = (const float4*)(in + s * D) + lane;
#pragma unroll
        for (int v = 0; v < V; v++) {
            float4 t = p[v * 32];
            acc[v].x = fmaf(c, t.x, acc[v].x);
            acc[v].y = fmaf(c, t.y, acc[v].y);
            acc[v].z = fmaf(c, t.z, acc[v].z);
            acc[v].w = fmaf(c, t.w, acc[v].w);
        }
    }
    float inv = g_ininv[warp];
#pragma unroll
    for (int v = 0; v < V; v++) {
        acc[v].x *= inv; acc[v].y *= inv; acc[v].z *= inv; acc[v].w *= inv;
        if (MODE >= 1) {
            acc[v].x = fmaxf(acc[v].x, 0.f);
            acc[v].y = fmaxf(acc[v].y, 0.f);
            acc[v].z = fmaxf(acc[v].z, 0.f);
            acc[v].w = fmaxf(acc[v].w, 0.f);
        }
    }
    if (MODE == 2) {
        int g = gid[warp];
        float* r = g_readout + g * OUTD + lane * 4;
        atomicAdd(r + 0, acc[0].x);
        atomicAdd(r + 1, acc[0].y);
        atomicAdd(r + 2, acc[0].z);
        atomicAdd(r + 3, acc[0].w);
    } else {
        float4* o = (float4*)(out + warp * D) + lane;
#pragma unroll
        for (int v = 0; v < V; v++) o[v * 32] = acc[v];
    }
}

// ---------------- packed-fp32x2 SGEMM: C[M,BN] = A[M,K] @ B[K,BN] ----------------
// BM=64 rows/block, BK=16, 256 threads; thread tile = 8 rows x PJ packed col-pairs.
// EPI 0: none, 1: relu, 2: LayerNorm(gamma,beta)+relu (BN==256 only)
template <int BN, int K, int EPI>
__global__ __launch_bounds__(256) void k_gemm(const float* __restrict__ A,
                                              const float* __restrict__ B,
                                              float* __restrict__ C, int ldC, int colOff,
                                              const float* __restrict__ gamma,
                                              const float* __restrict__ beta) {
    constexpr int BM = 64, BK = 16;
    constexpr int PJ = BN / 64;  // packed pairs per thread (4 for BN=256, 2 for BN=128)
    __shared__ unsigned long long As2[BK][BM];      // A value duplicated into both halves
    __shared__ unsigned long long Bs2[BK][BN / 2];  // natural column pairs
    int tid = threadIdx.x;
    int tr = tid >> 5, tc = tid & 31;
    int m0 = blockIdx.x * BM;
    unsigned long long acc[8][PJ];
#pragma unroll
    for (int i = 0; i < 8; i++)
#pragma unroll
        for (int j = 0; j < PJ; j++) acc[i][j] = 0ULL;

    const float* Ab = A + (long)m0 * K;
    for (int k0 = 0; k0 < K; k0 += BK) {
        {  // A tile: 64x16, one float4 per thread, stored transposed + duplicated
            int r = tid >> 2, kk = (tid & 3) << 2;
            float4 av = *(const float4*)(Ab + r * K + k0 + kk);
            As2[kk + 0][r] = packff(av.x, av.x);
            As2[kk + 1][r] = packff(av.y, av.y);
            As2[kk + 2][r] = packff(av.z, av.z);
            As2[kk + 3][r] = packff(av.w, av.w);
        }
        {  // B tile: 16xBN
            constexpr int NB4 = BN / 4;
            constexpr int ITER = (BK * NB4) / 256;
#pragma unroll
            for (int it = 0; it < ITER; it++) {
                int idx = tid + it * 256;
                int row = idx / NB4, c4 = idx % NB4;
                float4 bv = *(const float4*)(B + (k0 + row) * BN + c4 * 4);
                Bs2[row][c4 * 2 + 0] = packff(bv.x, bv.y);
                Bs2[row][c4 * 2 + 1] = packff(bv.z, bv.w);
            }
        }
        __syncthreads();
#pragma unroll
        for (int kk = 0; kk < BK; kk++) {
            unsigned long long a2[8], b2[PJ];
#pragma unroll
            for (int i = 0; i < 8; i++) a2[i] = As2[kk][tr * 8 + i];
#pragma unroll
            for (int j = 0; j < PJ; j++) b2[j] = Bs2[kk][tc + 32 * j];
#pragma unroll
            for (int i = 0; i < 8; i++)
#pragma unroll
                for (int j = 0; j < PJ; j++) ffma2(acc[i][j], a2[i], b2[j]);
        }
        __syncthreads();
    }

    if (EPI == 2) {
        // fused LayerNorm (over BN cols; one warp owns 8 full rows) + relu
#pragma unroll
        for (int i = 0; i < 8; i++) {
            float s = 0.f, ss = 0.f;
#pragma unroll
            for (int j = 0; j < PJ; j++) {
                float a = lo32(acc[i][j]), b = hi32(acc[i][j]);
                s += a + b;
                ss += a * a + b * b;
            }
#pragma unroll
            for (int o = 16; o > 0; o >>= 1) {
                s += __shfl_xor_sync(0xffffffffu, s, o);
                ss += __shfl_xor_sync(0xffffffffu, ss, o);
            }
            float mean = s * (1.f / BN);
            float var = ss * (1.f / BN) - mean * mean;
            float rstd = rsqrtf(var + 1e-5f);
            int row = m0 + tr * 8 + i;
#pragma unroll
            for (int j = 0; j < PJ; j++) {
                int c = 2 * (tc + 32 * j);
                float v0 = (lo32(acc[i][j]) - mean) * rstd * gamma[c] + beta[c];
                float v1 = (hi32(acc[i][j]) - mean) * rstd * gamma[c + 1] + beta[c + 1];
                v0 = fmaxf(v0, 0.f);
                v1 = fmaxf(v1, 0.f);
                *(float2*)(C + (long)row * ldC + colOff + c) = make_float2(v0, v1);
            }
        }
    } else {
#pragma unroll
        for (int i = 0; i < 8; i++) {
            int row = m0 + tr * 8 + i;
#pragma unroll
            for (int j = 0; j < PJ; j++) {
                int c = 2 * (tc + 32 * j);
                float v0 = lo32(acc[i][j]);
                float v1 = hi32(acc[i][j]);
                if (EPI == 1) { v0 = fmaxf(v0, 0.f); v1 = fmaxf(v1, 0.f); }
                *(float2*)(C + (long)row * ldC + colOff + c) = make_float2(v0, v1);
            }
        }
    }
}

// ---------------- readout normalize ----------------
__global__ void k_norm(float* __restrict__ out) {
    int b = blockIdx.x;
    int t = threadIdx.x;  // 128 threads
    float v = g_readout[b * OUTD + t];
    float ss = v * v;
#pragma unroll
    for (int o = 16; o > 0; o >>= 1) ss += __shfl_xor_sync(0xffffffffu, ss, o);
    __shared__ float sw[4];
    if ((t & 31) == 0) sw[t >> 5] = ss;
    __syncthreads();
    float tot = sw[0] + sw[1] + sw[2] + sw[3];
    float norm = fmaxf(sqrtf(tot), 1e-12f);
    out[b * OUTD + t] = v / norm;
}

// ---------------- launch ----------------
extern "C" void kernel_launch(void* const* d_in, const int* in_sizes, int n_in,
                              void* d_out, int out_size) {
    const float* x    = (const float*)d_in[0];
    const float* w    = (const float*)d_in[1];
    const float* W1   = (const float*)d_in[2];
    const float* fc1W = (const float*)d_in[3];
    const float* gam  = (const float*)d_in[4];
    const float* bet  = (const float*)d_in[5];
    const float* W2   = (const float*)d_in[6];
    const float* W3   = (const float*)d_in[7];
    const int*   src  = (const int*)d_in[8];
    const int*   dst  = (const int*)d_in[9];
    const int*   gid  = (const int*)d_in[10];
    float* out = (float*)d_out;

    float *p_agg1, *p_x1f1, *p_y2, *p_x2, *p_y3;
    cudaGetSymbolAddress((void**)&p_agg1, g_agg1);
    cudaGetSymbolAddress((void**)&p_x1f1, g_x1f1);
    cudaGetSymbolAddress((void**)&p_y2, g_y2);
    cudaGetSymbolAddress((void**)&p_x2, g_x2);
    cudaGetSymbolAddress((void**)&p_y3, g_y3);

    const int TB = 256;
    // graph preprocessing (per call; deterministic work)
    k_zero<<<(NN + TB - 1) / TB, TB>>>();
    k_deg<<<(NE + TB - 1) / TB, TB>>>(src, dst);
    k_inv<<<(NN + TB - 1) / TB, TB>>>();
    k_scan<<<1, 1024>>>();
    k_place<<<(NE + TB - 1) / TB, TB>>>(src, dst, w);

    const int AGG_BLK = (NN * 32 + TB - 1) / TB;  // one warp per node
    const int GEMM_BLK = NN / 64;                 // 625

    // layer 1: agg(x) @ 128 dims, then GEMM->256 with relu
    k_agg<IND, 0><<<AGG_BLK, TB>>>(x, p_agg1, nullptr);
    k_gemm<256, 128, 1><<<GEMM_BLK, TB>>>(p_agg1, W1, p_x1f1, CAT, 0, nullptr, nullptr);
    // fc1: GEMM + fused LN + relu, concat into cols [256,512)
    k_gemm<256, 128, 2><<<GEMM_BLK, TB>>>(x, fc1W, p_x1f1, CAT, H4, gam, bet);
    // layer 2: GEMM first (512->256), then agg at 256 dims with relu
    k_gemm<256, 512, 0><<<GEMM_BLK, TB>>>(p_x1f1, W2, p_y2, H4, 0, nullptr, nullptr);
    k_agg<H4, 1><<<AGG_BLK, TB>>>(p_y2, p_x2, nullptr);
    // layer 3: GEMM first (256->128), then agg at 128 dims + fused readout
    k_gemm<128, 256, 0><<<GEMM_BLK, TB>>>(p_x2, W3, p_y3, OUTD, 0, nullptr, nullptr);
    k_agg<OUTD, 2><<<AGG_BLK, TB>>>(p_y3, nullptr, gid);
    // final L2 normalize
    k_norm<<<NG, OUTD>>>(out);
}

// round 4
// speedup vs baseline: 1.6790x; 1.6790x over previous
#include <cuda_runtime.h>
#include <cuda_bf16.h>
#include <cstdint>

#define NN 40000
#define NE 320000
#define NG 64
#define IND 128
#define H4 256
#define OUTD 128
#define CAT 512

// ---------------- scratch (device globals; no allocation allowed) ----------------
__device__ int   g_outcnt[NN];
__device__ int   g_incnt[NN];
__device__ int   g_cursor[NN];
__device__ int   g_rowptr[NN + 1];
__device__ int   g_bsum[64];
__device__ float g_outinv[NN];
__device__ float g_ininv[NN];
__device__ int   g_es[NE];     // edge src, CSR-ordered by dst
__device__ float g_ec[NE];     // edge coef = max(w)*out_inv[src]
__device__ float g_agg1[NN * IND];
__device__ float g_x1f1[NN * CAT];
__device__ float g_y2[NN * H4];
__device__ float g_x2[NN * H4];
__device__ float g_y3[NN * OUTD];
__device__ float g_readout[NG * OUTD];
// weights pre-split to bf16 hi/lo, transposed to [N][K]
// layout: W1 @0 (32768), fc1 @32768 (32768), W2 @65536 (131072), W3 @196608 (32768)
__device__ __nv_bfloat16 g_bh[229376];
__device__ __nv_bfloat16 g_bl[229376];

// ---------------- helpers ----------------
__device__ __forceinline__ uint32_t smem_u32(const void* p) {
    uint32_t a;
    asm("{ .reg .u64 t; cvta.to.shared.u64 t, %1; cvt.u32.u64 %0, t; }" : "=r"(a) : "l"(p));
    return a;
}
__device__ __forceinline__ void cpa16(uint32_t dst, const void* src) {
    asm volatile("cp.async.cg.shared.global [%0], [%1], 16;" :: "r"(dst), "l"(src) : "memory");
}
__device__ __forceinline__ void cpa_commit() {
    asm volatile("cp.async.commit_group;" ::: "memory");
}
__device__ __forceinline__ void cpa_wait0() {
    asm volatile("cp.async.wait_group 0;" ::: "memory");
}
#define MMA16816(d, a, b)                                                     \
    asm volatile(                                                             \
        "mma.sync.aligned.m16n8k16.row.col.f32.bf16.bf16.f32 "                \
        "{%0,%1,%2,%3}, {%4,%5,%6,%7}, {%8,%9}, {%0,%1,%2,%3};"               \
        : "+f"((d)[0]), "+f"((d)[1]), "+f"((d)[2]), "+f"((d)[3])              \
        : "r"((a)[0]), "r"((a)[1]), "r"((a)[2]), "r"((a)[3]),                 \
          "r"((b)[0]), "r"((b)[1]))

__device__ __forceinline__ void cvt_sts8(const float* f, uint8_t* dh, uint8_t* dl) {
    union { unsigned short u[8]; uint4 v; } H, L;
#pragma unroll
    for (int j = 0; j < 8; j++) {
        __nv_bfloat16 h = __float2bfloat16(f[j]);
        H.u[j] = __bfloat16_as_ushort(h);
        L.u[j] = __bfloat16_as_ushort(__float2bfloat16(f[j] - __bfloat162float(h)));
    }
    *(uint4*)dh = H.v;
    *(uint4*)dl = L.v;
}

// ---------------- setup kernels ----------------
__global__ void k_zero() {
    int i = blockIdx.x * blockDim.x + threadIdx.x;
    if (i < NN) { g_outcnt[i] = 0; g_incnt[i] = 0; g_cursor[i] = 0; }
    if (i < NG * OUTD) g_readout[i] = 0.f;
}

__global__ void k_deg(const int* __restrict__ src, const int* __restrict__ dst) {
    int e = blockIdx.x * blockDim.x + threadIdx.x;
    if (e < NE) {
        atomicAdd(&g_outcnt[src[e]], 1);
        atomicAdd(&g_incnt[dst[e]], 1);
    }
}

__global__ void k_inv() {
    int i = blockIdx.x * blockDim.x + threadIdx.x;
    if (i < NN) {
        g_outinv[i] = rsqrtf((float)max(g_outcnt[i], 1));
        g_ininv[i]  = rsqrtf((float)max(g_incnt[i], 1));
    }
}

// multi-block scan
__global__ void k_scan_a() {
    __shared__ int sh[1024];
    int b = blockIdx.x, t = threadIdx.x;
    int idx = b * 1024 + t;
    int v = (idx < NN) ? g_incnt[idx] : 0;
    sh[t] = v;
    __syncthreads();
#pragma unroll
    for (int off = 1; off < 1024; off <<= 1) {
        int u = (t >= off) ? sh[t - off] : 0;
        __syncthreads();
        sh[t] += u;
        __syncthreads();
    }
    int incl = sh[t];
    if (idx <= NN) g_rowptr[idx] = incl - v;
    if (t == 1023) g_bsum[b] = incl;
}
__global__ void k_scan_b() {
    if (threadIdx.x == 0) {
        int s = 0;
        for (int i = 0; i < 40; i++) { int v = g_bsum[i]; g_bsum[i] = s; s += v; }
    }
}
__global__ void k_scan_c() {
    int idx = blockIdx.x * blockDim.x + threadIdx.x;
    if (idx <= NN) g_rowptr[idx] += g_bsum[idx >> 10];
}

__global__ void k_place(const int* __restrict__ src, const int* __restrict__ dst,
                        const float* __restrict__ w) {
    int e = blockIdx.x * blockDim.x + threadIdx.x;
    if (e >= NE) return;
    float4 ww = *(const float4*)(w + 4 * e);
    float m = fmaxf(fmaxf(ww.x, ww.y), fmaxf(ww.z, ww.w));
    int d = dst[e];
    int s = src[e];
    int pos = g_rowptr[d] + atomicAdd(&g_cursor[d], 1);
    g_es[pos] = s;
    g_ec[pos] = m * g_outinv[s];
}

// weights: fp32 [K][N] -> bf16 hi/lo [N][K]
__global__ void k_convB(const float* __restrict__ W, __nv_bfloat16* __restrict__ hi,
                        __nv_bfloat16* __restrict__ lo, int K, int N) {
    int idx = blockIdx.x * blockDim.x + threadIdx.x;
    if (idx >= K * N) return;
    int k = idx % K, n = idx / K;
    float x = W[k * N + n];
    __nv_bfloat16 h = __float2bfloat16(x);
    hi[idx] = h;
    lo[idx] = __float2bfloat16(x - __bfloat162float(h));
}

// ---------------- aggregation: one warp per dst node ----------------
template <int D, int MODE>
__global__ void k_agg(const float* __restrict__ in, float* __restrict__ out,
                      const int* __restrict__ gid) {
    int warp = (blockIdx.x * blockDim.x + threadIdx.x) >> 5;
    int lane = threadIdx.x & 31;
    if (warp >= NN) return;
    int beg = g_rowptr[warp];
    int end = g_rowptr[warp + 1];
    constexpr int V = D / 128;
    float4 acc[V];
#pragma unroll
    for (int v = 0; v < V; v++) acc[v] = make_float4(0.f, 0.f, 0.f, 0.f);
    for (int e = beg; e < end; e++) {
        int s = g_es[e];
        float c = g_ec[e];
        const float4* p = (const float4*)(in + s * D) + lane;
#pragma unroll
        for (int v = 0; v < V; v++) {
            float4 t = p[v * 32];
            acc[v].x = fmaf(c, t.x, acc[v].x);
            acc[v].y = fmaf(c, t.y, acc[v].y);
            acc[v].z = fmaf(c, t.z, acc[v].z);
            acc[v].w = fmaf(c, t.w, acc[v].w);
        }
    }
    float inv = g_ininv[warp];
#pragma unroll
    for (int v = 0; v < V; v++) {
        acc[v].x *= inv; acc[v].y *= inv; acc[v].z *= inv; acc[v].w *= inv;
        if (MODE >= 1) {
            acc[v].x = fmaxf(acc[v].x, 0.f);
            acc[v].y = fmaxf(acc[v].y, 0.f);
            acc[v].z = fmaxf(acc[v].z, 0.f);
            acc[v].w = fmaxf(acc[v].w, 0.f);
        }
    }
    if (MODE == 2) {
        int g = gid[warp];
        float* r = g_readout + g * OUTD + lane * 4;
        atomicAdd(r + 0, acc[0].x);
        atomicAdd(r + 1, acc[0].y);
        atomicAdd(r + 2, acc[0].z);
        atomicAdd(r + 3, acc[0].w);
    } else {
        float4* o = (float4*)(out + warp * D) + lane;
#pragma unroll
        for (int v = 0; v < V; v++) o[v * 32] = acc[v];
    }
}

// ---------------- mma.sync split-bf16 GEMM ----------------
// C[M,N] = A[M,K]@W[K,N] via Ah*Bh + Ah*Bl + Al*Bh, fp32 accum.
// Block tile 128x128, BKf=16 fp32 per stage, double buffered.
// B pre-split bf16 in [N][K]. smem rows padded to 24 bf16 (48B) -> conflict-free LDS.
template <int K, int RELU>
__global__ __launch_bounds__(256, 2) void k_mma(
    const float* __restrict__ A,
    const __nv_bfloat16* __restrict__ Bh_g, const __nv_bfloat16* __restrict__ Bl_g,
    float* __restrict__ C, int ldC, int colOff) {
    extern __shared__ __align__(16) uint8_t smem[];
    constexpr int NC = K / 16;
    constexpr int STG = 24576;
    constexpr int AH = 0, AL = 6144, BH = 12288, BL = 18432;
    const int tid = threadIdx.x;
    const int wid = tid >> 5, lane = tid & 31;
    const int wm = wid & 3, wn = wid >> 2;
    const int g = lane >> 2, q = lane & 3;
    const int m0 = blockIdx.x * 128;
    const int nblk = blockIdx.y * 128;
    const uint32_t sb = smem_u32(smem);

    float acc[2][8][4];
#pragma unroll
    for (int mi = 0; mi < 2; mi++)
#pragma unroll
        for (int ni = 0; ni < 8; ni++)
#pragma unroll
            for (int r = 0; r < 4; r++) acc[mi][ni][r] = 0.f;

    // loader mapping
    const int ar = tid >> 1, ah_ = tid & 1;   // A: row 0..127, k-half 0/1
    const int br = tid & 127, bw = tid >> 7;  // B: row 0..127, hi/lo select
    const int arow = m0 + ar;
    const float* asrc = A + (long)arow * K + ah_ * 8;
    const uint32_t adst_h = AH + (uint32_t)ar * 48 + ah_ * 16;
    const uint32_t adst_l = AL + (uint32_t)ar * 48 + ah_ * 16;
    const __nv_bfloat16* bsrc = (bw ? Bl_g : Bh_g) + (long)(nblk + br) * K;
    const uint32_t bdst = (bw ? BL : BH) + (uint32_t)br * 48;

    // prologue: fill stage 0
    {
        float f[8];
        if (arow < NN) {
            float4 va = *(const float4*)asrc;
            float4 vb = *(const float4*)(asrc + 4);
            f[0] = va.x; f[1] = va.y; f[2] = va.z; f[3] = va.w;
            f[4] = vb.x; f[5] = vb.y; f[6] = vb.z; f[7] = vb.w;
        } else {
#pragma unroll
            for (int j = 0; j < 8; j++) f[j] = 0.f;
        }
        cvt_sts8(f, smem + adst_h, smem + adst_l);
        cpa16(sb + bdst, bsrc);
        cpa16(sb + bdst + 16, bsrc + 8);
        cpa_commit();
    }

    for (int c = 0; c < NC; c++) {
        cpa_wait0();
        __syncthreads();
        uint8_t* stp = smem + (c & 1) * STG;
        const bool pf = (c + 1 < NC);
        float f[8];
        if (pf) {
            const float* ap = asrc + (c + 1) * 16;
            if (arow < NN) {
                float4 va = *(const float4*)ap;
                float4 vb = *(const float4*)(ap + 4);
                f[0] = va.x; f[1] = va.y; f[2] = va.z; f[3] = va.w;
                f[4] = vb.x; f[5] = vb.y; f[6] = vb.z; f[7] = vb.w;
            } else {
#pragma unroll
                for (int j = 0; j < 8; j++) f[j] = 0.f;
            }
            uint32_t nst = sb + ((c + 1) & 1) * STG;
            const __nv_bfloat16* bp = bsrc + (c + 1) * 16;
            cpa16(nst + bdst, bp);
            cpa16(nst + bdst + 16, bp + 8);
            cpa_commit();
        }
        // ---- compute stage c: (Ah,Bh), (Ah,Bl), (Al,Bh) ----
        uint32_t af[2][4], bf[8][2];
#pragma unroll
        for (int mi = 0; mi < 2; mi++) {
            uint32_t o = (uint32_t)(wm * 32 + mi * 16 + g) * 48 + q * 4;
            af[mi][0] = *(const uint32_t*)(stp + AH + o);
            af[mi][1] = *(const uint32_t*)(stp + AH + o + 384);
            af[mi][2] = *(const uint32_t*)(stp + AH + o + 16);
            af[mi][3] = *(const uint32_t*)(stp + AH + o + 400);
        }
#pragma unroll
        for (int ni = 0; ni < 8; ni++) {
            uint32_t o = (uint32_t)(wn * 64 + ni * 8 + g) * 48 + q * 4;
            bf[ni][0] = *(const uint32_t*)(stp + BH + o);
            bf[ni][1] = *(const uint32_t*)(stp + BH + o + 16);
        }
#pragma unroll
        for (int mi = 0; mi < 2; mi++)
#pragma unroll
            for (int ni = 0; ni < 8; ni++) MMA16816(acc[mi][ni], af[mi], bf[ni]);
#pragma unroll
        for (int ni = 0; ni < 8; ni++) {
            uint32_t o = (uint32_t)(wn * 64 + ni * 8 + g) * 48 + q * 4;
            bf[ni][0] = *(const uint32_t*)(stp + BL + o);
            bf[ni][1] = *(const uint32_t*)(stp + BL + o + 16);
        }
#pragma unroll
        for (int mi = 0; mi < 2; mi++)
#pragma unroll
            for (int ni = 0; ni < 8; ni++) MMA16816(acc[mi][ni], af[mi], bf[ni]);
#pragma unroll
        for (int mi = 0; mi < 2; mi++) {
            uint32_t o = (uint32_t)(wm * 32 + mi * 16 + g) * 48 + q * 4;
            af[mi][0] = *(const uint32_t*)(stp + AL + o);
            af[mi][1] = *(const uint32_t*)(stp + AL + o + 384);
            af[mi][2] = *(const uint32_t*)(stp + AL + o + 16);
            af[mi][3] = *(const uint32_t*)(stp + AL + o + 400);
        }
#pragma unroll
        for (int ni = 0; ni < 8; ni++) {
            uint32_t o = (uint32_t)(wn * 64 + ni * 8 + g) * 48 + q * 4;
            bf[ni][0] = *(const uint32_t*)(stp + BH + o);
            bf[ni][1] = *(const uint32_t*)(stp + BH + o + 16);
        }
#pragma unroll
        for (int mi = 0; mi < 2; mi++)
#pragma unroll
            for (int ni = 0; ni < 8; ni++) MMA16816(acc[mi][ni], af[mi], bf[ni]);

        if (pf) {
            uint8_t* nstp = smem + ((c + 1) & 1) * STG;
            cvt_sts8(f, nstp + adst_h, nstp + adst_l);
        }
    }

    // epilogue
#pragma unroll
    for (int mi = 0; mi < 2; mi++)
#pragma unroll
        for (int ni = 0; ni < 8; ni++) {
            int r0 = m0 + wm * 32 + mi * 16 + g;
            int cc = colOff + nblk + wn * 64 + ni * 8 + 2 * q;
            float v0 = acc[mi][ni][0], v1 = acc[mi][ni][1];
            float v2 = acc[mi][ni][2], v3 = acc[mi][ni][3];
            if (RELU) {
                v0 = fmaxf(v0, 0.f); v1 = fmaxf(v1, 0.f);
                v2 = fmaxf(v2, 0.f); v3 = fmaxf(v3, 0.f);
            }
            if (r0 < NN)     *(float2*)(C + (long)r0 * ldC + cc)       = make_float2(v0, v1);
            if (r0 + 8 < NN) *(float2*)(C + (long)(r0 + 8) * ldC + cc) = make_float2(v2, v3);
        }
}

// ---------------- LayerNorm + ReLU over x1f1 cols [256,512), one warp per row ----------------
__global__ void k_ln(float* __restrict__ X, const float* __restrict__ gamma,
                     const float* __restrict__ beta) {
    int warp = (blockIdx.x * blockDim.x + threadIdx.x) >> 5;
    int lane = threadIdx.x & 31;
    if (warp >= NN) return;
    float* row = X + (long)warp * CAT + H4;
    float4 v0 = ((float4*)row)[lane];
    float4 v1 = ((float4*)row)[lane + 32];
    float s = v0.x + v0.y + v0.z + v0.w + v1.x + v1.y + v1.z + v1.w;
    float ss = v0.x * v0.x + v0.y * v0.y + v0.z * v0.z + v0.w * v0.w +
               v1.x * v1.x + v1.y * v1.y + v1.z * v1.z + v1.w * v1.w;
#pragma unroll
    for (int o = 16; o > 0; o >>= 1) {
        s += __shfl_xor_sync(0xffffffffu, s, o);
        ss += __shfl_xor_sync(0xffffffffu, ss, o);
    }
    float mean = s * (1.f / 256.f);
    float var = ss * (1.f / 256.f) - mean * mean;
    float rstd = rsqrtf(var + 1e-5f);
    float4 g0 = ((const float4*)gamma)[lane], g1 = ((const float4*)gamma)[lane + 32];
    float4 b0 = ((const float4*)beta)[lane], b1 = ((const float4*)beta)[lane + 32];
    v0.x = fmaxf((v0.x - mean) * rstd * g0.x + b0.x, 0.f);
    v0.y = fmaxf((v0.y - mean) * rstd * g0.y + b0.y, 0.f);
    v0.z = fmaxf((v0.z - mean) * rstd * g0.z + b0.z, 0.f);
    v0.w = fmaxf((v0.w - mean) * rstd * g0.w + b0.w, 0.f);
    v1.x = fmaxf((v1.x - mean) * rstd * g1.x + b1.x, 0.f);
    v1.y = fmaxf((v1.y - mean) * rstd * g1.y + b1.y, 0.f);
    v1.z = fmaxf((v1.z - mean) * rstd * g1.z + b1.z, 0.f);
    v1.w = fmaxf((v1.w - mean) * rstd * g1.w + b1.w, 0.f);
    ((float4*)row)[lane] = v0;
    ((float4*)row)[lane + 32] = v1;
}

// ---------------- readout normalize ----------------
__global__ void k_norm(float* __restrict__ out) {
    int b = blockIdx.x;
    int t = threadIdx.x;  // 128 threads
    float v = g_readout[b * OUTD + t];
    float ss = v * v;
#pragma unroll
    for (int o = 16; o > 0; o >>= 1) ss += __shfl_xor_sync(0xffffffffu, ss, o);
    __shared__ float sw[4];
    if ((t & 31) == 0) sw[t >> 5] = ss;
    __syncthreads();
    float tot = sw[0] + sw[1] + sw[2] + sw[3];
    float norm = fmaxf(sqrtf(tot), 1e-12f);
    out[b * OUTD + t] = v / norm;
}

// ---------------- launch ----------------
extern "C" void kernel_launch(void* const* d_in, const int* in_sizes, int n_in,
                              void* d_out, int out_size) {
    const float* x    = (const float*)d_in[0];
    const float* w    = (const float*)d_in[1];
    const float* W1   = (const float*)d_in[2];
    const float* fc1W = (const float*)d_in[3];
    const float* gam  = (const float*)d_in[4];
    const float* bet  = (const float*)d_in[5];
    const float* W2   = (const float*)d_in[6];
    const float* W3   = (const float*)d_in[7];
    const int*   src  = (const int*)d_in[8];
    const int*   dst  = (const int*)d_in[9];
    const int*   gid  = (const int*)d_in[10];
    float* out = (float*)d_out;

    float *p_agg1, *p_x1f1, *p_y2, *p_x2, *p_y3;
    __nv_bfloat16 *p_bh, *p_bl;
    cudaGetSymbolAddress((void**)&p_agg1, g_agg1);
    cudaGetSymbolAddress((void**)&p_x1f1, g_x1f1);
    cudaGetSymbolAddress((void**)&p_y2, g_y2);
    cudaGetSymbolAddress((void**)&p_x2, g_x2);
    cudaGetSymbolAddress((void**)&p_y3, g_y3);
    cudaGetSymbolAddress((void**)&p_bh, g_bh);
    cudaGetSymbolAddress((void**)&p_bl, g_bl);

    const int SMEM = 49152;
    cudaFuncSetAttribute(k_mma<128, 1>, cudaFuncAttributeMaxDynamicSharedMemorySize, SMEM);
    cudaFuncSetAttribute(k_mma<128, 0>, cudaFuncAttributeMaxDynamicSharedMemorySize, SMEM);
    cudaFuncSetAttribute(k_mma<512, 0>, cudaFuncAttributeMaxDynamicSharedMemorySize, SMEM);
    cudaFuncSetAttribute(k_mma<256, 0>, cudaFuncAttributeMaxDynamicSharedMemorySize, SMEM);

    const int TB = 256;
    // graph preprocessing
    k_zero<<<(NN + TB - 1) / TB, TB>>>();
    k_deg<<<(NE + TB - 1) / TB, TB>>>(src, dst);
    k_inv<<<(NN + TB - 1) / TB, TB>>>();
    k_scan_a<<<40, 1024>>>();
    k_scan_b<<<1, 32>>>();
    k_scan_c<<<40, 1024>>>();
    k_place<<<(NE + TB - 1) / TB, TB>>>(src, dst, w);
    // weight split/transpose to bf16 hi/lo
    k_convB<<<(128 * 256 + TB - 1) / TB, TB>>>(W1,   p_bh + 0,      p_bl + 0,      128, 256);
    k_convB<<<(128 * 256 + TB - 1) / TB, TB>>>(fc1W, p_bh + 32768,  p_bl + 32768,  128, 256);
    k_convB<<<(512 * 256 + TB - 1) / TB, TB>>>(W2,   p_bh + 65536,  p_bl + 65536,  512, 256);
    k_convB<<<(256 * 128 + TB - 1) / TB, TB>>>(W3,   p_bh + 196608, p_bl + 196608, 256, 128);

    const int AGG_BLK = (NN * 32 + TB - 1) / TB;  // one warp per node
    const int GX = (NN + 127) / 128;              // 313

    // layer 1: agg(x) at 128 dims, then GEMM 128->256 + relu into x1f1[:,0:256)
    k_agg<IND, 0><<<AGG_BLK, TB>>>(x, p_agg1, nullptr);
    k_mma<128, 1><<<dim3(GX, 2), TB, SMEM>>>(p_agg1, p_bh + 0, p_bl + 0, p_x1f1, CAT, 0);
    // fc1: GEMM raw into x1f1[:,256:512), then LN+relu in place
    k_mma<128, 0><<<dim3(GX, 2), TB, SMEM>>>(x, p_bh + 32768, p_bl + 32768, p_x1f1, CAT, H4);
    k_ln<<<(NN * 32 + TB - 1) / TB, TB>>>(p_x1f1, gam, bet);
    // layer 2: GEMM 512->256, then agg at 256 dims + relu
    k_mma<512, 0><<<dim3(GX, 2), TB, SMEM>>>(p_x1f1, p_bh + 65536, p_bl + 65536, p_y2, H4, 0);
    k_agg<H4, 1><<<AGG_BLK, TB>>>(p_y2, p_x2, nullptr);
    // layer 3: GEMM 256->128, then agg at 128 dims + relu + fused readout
    k_mma<256, 0><<<dim3(GX, 1), TB, SMEM>>>(p_x2, p_bh + 196608, p_bl + 196608, p_y3, OUTD, 0);
    k_agg<OUTD, 2><<<AGG_BLK, TB>>>(p_y3, nullptr, gid);
    // final L2 normalize
    k_norm<<<NG, OUTD>>>(out);
}